// round 9
// baseline (speedup 1.0000x reference)
#include <cuda_runtime.h>

// MultiClassDiceScore: histograms over 33.5M voxels, SIMD nibble/PRMT,
// fused finalize. Memory-bound: 268 MB streamed once.
// cp.async (LDGSTS) 3-stage smem pipeline: in-flight loads live in smem,
// not registers -> MLP no longer capped by the 32-reg budget.
// Each thread prefetches and consumes ONLY its own 16B+16B per stage, so
// no __syncthreads in the stream loop - just cp.async.wait_group.
//
// g_hist: [0..3]=den1+den2 for c0..3, [4..7]=num c0..3, [8]=total agreements.
// Class-4 bins derived in finalize; last block resets state for graph replay.

#define DICE_EPS 1e-7f
#define GRID_BLOCKS 1184   // 148 SMs x 8 CTAs: one full wave
#define STAGES 3

__device__ unsigned int g_hist[12];   // zero-initialized at module load
__device__ unsigned int g_done;       // block-completion counter

__device__ __forceinline__ unsigned int prmt(unsigned int a, unsigned int b, unsigned int s) {
    unsigned int d;
    asm("prmt.b32 %0, %1, %2, %3;" : "=r"(d) : "r"(a), "r"(b), "r"(s));
    return d;
}

__device__ __forceinline__ unsigned long long addf32x2(unsigned long long a, unsigned long long b) {
    unsigned long long d;
    asm("add.rn.f32x2 %0, %1, %2;" : "=l"(d) : "l"(a), "l"(b));
    return d;
}

__device__ __forceinline__ void cp_async16(void* smem_dst, const void* gsrc) {
    unsigned int sa = (unsigned int)__cvta_generic_to_shared(smem_dst);
    asm volatile("cp.async.cg.shared.global [%0], [%1], 16;" :: "r"(sa), "l"(gsrc) : "memory");
}

// Pack constants: lo half adds 2^23 (label -> bits[0:4)), hi half adds 2^19
// (label -> bits[4:8)), etc. All sums exact in fp32 for labels 0..4.
#define C01 0x490000004B000000ull   // {2^23, 2^19}
#define C23 0x4500000047000000ull   // {2^15, 2^11}

__global__ __launch_bounds__(256, 8)
void dice_main_kernel(const ulonglong2* __restrict__ pred2,
                      const int4* __restrict__ mask4,
                      int nvec, int n_total,
                      float* __restrict__ out) {
    __shared__ __align__(16) ulonglong2 pbuf[STAGES][256];
    __shared__ __align__(16) int4       mbuf[STAGES][256];

    // Byte-lane accumulators. Max per-thread groups <=28; aS bytes <= 56,
    // aN/aZ <= 28 - far below 255, no overflow.
    unsigned int aS0 = 0, aS1 = 0, aS2 = 0, aS3 = 0;   // (p==c) + (m==c)
    unsigned int aN0 = 0, aN1 = 0, aN2 = 0, aN3 = 0;   // p==m==c
    unsigned int aZ  = 0;                              // p==m (any class)

    const int t = threadIdx.x;
    const int stride = gridDim.x * blockDim.x;
    const int idx0 = blockIdx.x * blockDim.x + t;

    // Prologue: prefetch stages 0 and 1 (one commit group per stage).
    {
        int g0 = idx0;
        if (g0 < nvec) { cp_async16(&pbuf[0][t], &pred2[g0]); cp_async16(&mbuf[0][t], &mask4[g0]); }
        asm volatile("cp.async.commit_group;" ::: "memory");
        int g1 = idx0 + stride;
        if (g1 < nvec) { cp_async16(&pbuf[1][t], &pred2[g1]); cp_async16(&mbuf[1][t], &mask4[g1]); }
        asm volatile("cp.async.commit_group;" ::: "memory");
    }

    int gi = idx0;
    int s  = 0;
#pragma unroll 3
    for (; gi < nvec; gi += stride, ++s) {
        // Issue stage s+2 (slot rotates mod 3), then wait so stage s is ready.
        int gnext = gi + 2 * stride;
        int slot_next = (s + 2) % STAGES;
        if (gnext < nvec) {
            cp_async16(&pbuf[slot_next][t], &pred2[gnext]);
            cp_async16(&mbuf[slot_next][t], &mask4[gnext]);
        }
        asm volatile("cp.async.commit_group;" ::: "memory");
        asm volatile("cp.async.wait_group 2;" ::: "memory");

        int cur = s % STAGES;
        ulonglong2 p = pbuf[cur][t];   // 4 float labels (this thread's own bytes)
        int4       m = mbuf[cur][t];   // 4 int labels

        // selP nibbles = [p0,p1,p2,p3] via packed-f32 exponent trick.
        unsigned long long a01 = addf32x2(p.x, C01);
        unsigned long long a23 = addf32x2(p.y, C23);
        unsigned int selP = (unsigned int)a01 | (unsigned int)(a01 >> 32)
                          | (unsigned int)a23 | (unsigned int)(a23 >> 32);
        // selM nibbles = [m0,m1,m2,m3]
        unsigned int selM = (unsigned int)m.x + ((unsigned int)m.y << 4)
                          + ((unsigned int)m.z << 8) + ((unsigned int)m.w << 12);

        // zd byte k = 1 iff p_k == m_k  (nibble-zero detect, one PRMT LUT)
        unsigned int zd = prmt(0x00000001u, 0u, selP ^ selM);
        aZ += zd;

        // per-class equality bytes via PRMT LUTs (classes 0..3; 4 derived)
        unsigned int eP0 = prmt(0x00000001u, 0u, selP);
        unsigned int eP1 = prmt(0x00000100u, 0u, selP);
        unsigned int eP2 = prmt(0x00010000u, 0u, selP);
        unsigned int eP3 = prmt(0x01000000u, 0u, selP);

        aS0 += eP0 + prmt(0x00000001u, 0u, selM);
        aS1 += eP1 + prmt(0x00000100u, 0u, selM);
        aS2 += eP2 + prmt(0x00010000u, 0u, selM);
        aS3 += eP3 + prmt(0x01000000u, 0u, selM);

        aN0 += eP0 & zd; aN1 += eP1 & zd; aN2 += eP2 & zd; aN3 += eP3 & zd;
    }
    // Drain outstanding groups (none of their data is consumed).
    asm volatile("cp.async.wait_group 0;" ::: "memory");

    // Horizontal byte sums, warp reduce, block reduce, 9 global atomics/block.
    unsigned int v[9];
    v[0] = (unsigned int)__dp4a((int)aS0, 0x01010101, 0);
    v[1] = (unsigned int)__dp4a((int)aS1, 0x01010101, 0);
    v[2] = (unsigned int)__dp4a((int)aS2, 0x01010101, 0);
    v[3] = (unsigned int)__dp4a((int)aS3, 0x01010101, 0);
    v[4] = (unsigned int)__dp4a((int)aN0, 0x01010101, 0);
    v[5] = (unsigned int)__dp4a((int)aN1, 0x01010101, 0);
    v[6] = (unsigned int)__dp4a((int)aN2, 0x01010101, 0);
    v[7] = (unsigned int)__dp4a((int)aN3, 0x01010101, 0);
    v[8] = (unsigned int)__dp4a((int)aZ,  0x01010101, 0);

    __shared__ unsigned int sh[9];
    __shared__ bool is_last;
    if (threadIdx.x < 9) sh[threadIdx.x] = 0u;
    __syncthreads();

#pragma unroll
    for (int k = 0; k < 9; k++) {
        unsigned int w = __reduce_add_sync(0xFFFFFFFFu, v[k]);
        if ((threadIdx.x & 31) == 0) atomicAdd(&sh[k], w);
    }
    __syncthreads();
    if (threadIdx.x < 9) atomicAdd(&g_hist[threadIdx.x], sh[threadIdx.x]);

    // Last-block-done: the final arriving block computes dice + resets state.
    if (threadIdx.x == 0) {
        __threadfence();
        unsigned int old = atomicAdd(&g_done, 1u);
        is_last = (old == (unsigned int)(gridDim.x - 1));
    }
    __syncthreads();

    if (is_last && threadIdx.x == 0) {
        unsigned int S[5], Nm[5];
        unsigned int ss = 0, sn = 0;
#pragma unroll
        for (int c = 0; c < 4; c++) {
            S[c]  = g_hist[c];       ss += S[c];
            Nm[c] = g_hist[4 + c];   sn += Nm[c];
        }
        unsigned int Z = g_hist[8];
        S[4]  = 2u * (unsigned int)n_total - ss;   // den1[4]+den2[4]
        Nm[4] = Z - sn;

        float s2 = 0.0f;
#pragma unroll
        for (int c = 0; c < 5; c++) {
            s2 += 2.0f * (((float)Nm[c] + DICE_EPS) / ((float)S[c] + DICE_EPS));
        }
        out[0] = s2 * 0.2f;

        // reset state for the next (graph-replayed) launch
#pragma unroll
        for (int k = 0; k < 12; k++) g_hist[k] = 0u;
        __threadfence();
        g_done = 0u;
    }
}

extern "C" void kernel_launch(void* const* d_in, const int* in_sizes, int n_in,
                              void* d_out, int out_size) {
    const float* pred = (const float*)d_in[0];  // [128,1,512,512] f32, values 0..4
    const int*   mask = (const int*)d_in[1];    // [1,128,512,512] i32, values 0..4
    int n = in_sizes[0];                        // 33,554,432 (divisible by 4)
    int nvec = n >> 2;

    dice_main_kernel<<<GRID_BLOCKS, 256>>>((const ulonglong2*)pred,
                                           (const int4*)mask,
                                           nvec, n, (float*)d_out);
}

// round 10
// speedup vs baseline: 1.0449x; 1.0449x over previous
#include <cuda_runtime.h>

// MultiClassDiceScore: histograms over 33.5M voxels, SIMD nibble/PRMT,
// fused finalize. Memory-bound: 268 MB streamed once.
// cp.async.bulk (UBLKCP) 3-stage smem ring: 2 bulk copies per 8KB stage per
// CTA (vs thousands of per-thread loads). In-flight bytes live in smem, fully
// decoupled from the consumer dependency chain; consumers do conflict-free
// LDS.128 + the proven R5 PRMT body.
//
// g_hist: [0..3]=den1+den2 for c0..3, [4..7]=num c0..3, [8]=total agreements.
// Class-4 bins derived in finalize; last block resets state for graph replay.

#define DICE_EPS 1e-7f
#define GRID_BLOCKS 1184      // 148 SMs x 8 CTAs: one full wave
#define STAGES 3
#define CHUNK_GROUPS 256      // 256 x 16B per array per stage = 4KB + 4KB
#define CHUNK_BYTES 4096

__device__ unsigned int g_hist[12];   // zero-initialized at module load
__device__ unsigned int g_done;       // block-completion counter

__device__ __forceinline__ unsigned int prmt(unsigned int a, unsigned int b, unsigned int s) {
    unsigned int d;
    asm("prmt.b32 %0, %1, %2, %3;" : "=r"(d) : "r"(a), "r"(b), "r"(s));
    return d;
}

__device__ __forceinline__ unsigned long long addf32x2(unsigned long long a, unsigned long long b) {
    unsigned long long d;
    asm("add.rn.f32x2 %0, %1, %2;" : "=l"(d) : "l"(a), "l"(b));
    return d;
}

__device__ __forceinline__ void mbar_init(unsigned int mbar, unsigned int count) {
    asm volatile("mbarrier.init.shared.b64 [%0], %1;" :: "r"(mbar), "r"(count) : "memory");
}
__device__ __forceinline__ void mbar_expect_tx(unsigned int mbar, unsigned int bytes) {
    asm volatile("mbarrier.arrive.expect_tx.shared.b64 _, [%0], %1;"
                 :: "r"(mbar), "r"(bytes) : "memory");
}
__device__ __forceinline__ void bulk_g2s(unsigned int sdst, const void* gsrc,
                                         unsigned int bytes, unsigned int mbar) {
    asm volatile("cp.async.bulk.shared::cta.global.mbarrier::complete_tx::bytes "
                 "[%0], [%1], %2, [%3];"
                 :: "r"(sdst), "l"(gsrc), "r"(bytes), "r"(mbar) : "memory");
}
__device__ __forceinline__ void mbar_wait(unsigned int mbar, unsigned int parity) {
    asm volatile(
        "{\n\t"
        ".reg .pred P;\n\t"
        "WAIT_%=:\n\t"
        "mbarrier.try_wait.parity.acquire.cta.shared::cta.b64 P, [%0], %1, 0x989680;\n\t"
        "@P bra DONE_%=;\n\t"
        "bra WAIT_%=;\n\t"
        "DONE_%=:\n\t"
        "}" :: "r"(mbar), "r"(parity) : "memory");
}

// Pack constants: lo half adds 2^23 (label -> bits[0:4)), hi half adds 2^19
// (label -> bits[4:8)), etc. All sums exact in fp32 for labels 0..4.
#define C01 0x490000004B000000ull   // {2^23, 2^19}
#define C23 0x4500000047000000ull   // {2^15, 2^11}

__global__ __launch_bounds__(256, 8)
void dice_main_kernel(const ulonglong2* __restrict__ pred2,
                      const int4* __restrict__ mask4,
                      int nvec, int n_total,
                      float* __restrict__ out) {
    __shared__ __align__(16) ulonglong2 pbuf[STAGES][CHUNK_GROUPS];
    __shared__ __align__(16) int4       mbuf[STAGES][CHUNK_GROUPS];
    __shared__ __align__(8)  unsigned long long mbar_s[STAGES];

    const int t = threadIdx.x;
    const int bid = blockIdx.x;
    const int nchunks = nvec / CHUNK_GROUPS;   // 32768 (nvec = 8388608)
    // stages this CTA runs: chunks bid, bid+GRID, ...
    const int nstages = (nchunks - 1 - bid) / GRID_BLOCKS + 1;

    unsigned int mb0 = (unsigned int)__cvta_generic_to_shared(&mbar_s[0]);

    if (t == 0) {
#pragma unroll
        for (int k = 0; k < STAGES; k++) mbar_init(mb0 + 8u * k, 1u);
    }
    __syncthreads();

    // Prologue: issue stages 0 and 1.
    if (t == 0) {
#pragma unroll
        for (int s = 0; s < 2; s++) {
            if (s < nstages) {
                int c = bid + s * GRID_BLOCKS;
                unsigned int mb = mb0 + 8u * s;
                mbar_expect_tx(mb, 2u * CHUNK_BYTES);
                bulk_g2s((unsigned int)__cvta_generic_to_shared(&pbuf[s][0]),
                         pred2 + (size_t)c * CHUNK_GROUPS, CHUNK_BYTES, mb);
                bulk_g2s((unsigned int)__cvta_generic_to_shared(&mbuf[s][0]),
                         mask4 + (size_t)c * CHUNK_GROUPS, CHUNK_BYTES, mb);
            }
        }
    }

    // Byte-lane accumulators. Groups per thread = nstages (<=28);
    // aS bytes <= 56, aN/aZ <= 28 — far below 255, no overflow.
    unsigned int aS0 = 0, aS1 = 0, aS2 = 0, aS3 = 0;   // (p==c) + (m==c)
    unsigned int aN0 = 0, aN1 = 0, aN2 = 0, aN3 = 0;   // p==m==c
    unsigned int aZ  = 0;                              // p==m (any class)

    for (int s = 0; s < nstages; s++) {
        int slot = s % STAGES;
        mbar_wait(mb0 + 8u * slot, (unsigned int)((s / STAGES) & 1));

        ulonglong2 p = pbuf[slot][t];   // this thread's 4 float labels
        int4       m = mbuf[slot][t];   // this thread's 4 int labels

        // selP nibbles = [p0,p1,p2,p3] via packed-f32 exponent trick.
        unsigned long long a01 = addf32x2(p.x, C01);
        unsigned long long a23 = addf32x2(p.y, C23);
        unsigned int selP = (unsigned int)a01 | (unsigned int)(a01 >> 32)
                          | (unsigned int)a23 | (unsigned int)(a23 >> 32);
        // selM nibbles = [m0,m1,m2,m3]
        unsigned int selM = (unsigned int)m.x + ((unsigned int)m.y << 4)
                          + ((unsigned int)m.z << 8) + ((unsigned int)m.w << 12);

        // zd byte k = 1 iff p_k == m_k  (nibble-zero detect, one PRMT LUT)
        unsigned int zd = prmt(0x00000001u, 0u, selP ^ selM);
        aZ += zd;

        // per-class equality bytes via PRMT LUTs (classes 0..3; 4 derived)
        unsigned int eP0 = prmt(0x00000001u, 0u, selP);
        unsigned int eP1 = prmt(0x00000100u, 0u, selP);
        unsigned int eP2 = prmt(0x00010000u, 0u, selP);
        unsigned int eP3 = prmt(0x01000000u, 0u, selP);

        aS0 += eP0 + prmt(0x00000001u, 0u, selM);
        aS1 += eP1 + prmt(0x00000100u, 0u, selM);
        aS2 += eP2 + prmt(0x00010000u, 0u, selM);
        aS3 += eP3 + prmt(0x01000000u, 0u, selM);

        aN0 += eP0 & zd; aN1 += eP1 & zd; aN2 += eP2 & zd; aN3 += eP3 & zd;

        // All threads done with this slot before it can be refilled.
        __syncthreads();

        int s2 = s + 2;
        if (s2 < nstages && t == 0) {
            int c = bid + s2 * GRID_BLOCKS;
            int slot2 = s2 % STAGES;
            unsigned int mb = mb0 + 8u * slot2;
            mbar_expect_tx(mb, 2u * CHUNK_BYTES);
            bulk_g2s((unsigned int)__cvta_generic_to_shared(&pbuf[slot2][0]),
                     pred2 + (size_t)c * CHUNK_GROUPS, CHUNK_BYTES, mb);
            bulk_g2s((unsigned int)__cvta_generic_to_shared(&mbuf[slot2][0]),
                     mask4 + (size_t)c * CHUNK_GROUPS, CHUNK_BYTES, mb);
        }
    }

    // Horizontal byte sums, warp reduce, block reduce, 9 global atomics/block.
    unsigned int v[9];
    v[0] = (unsigned int)__dp4a((int)aS0, 0x01010101, 0);
    v[1] = (unsigned int)__dp4a((int)aS1, 0x01010101, 0);
    v[2] = (unsigned int)__dp4a((int)aS2, 0x01010101, 0);
    v[3] = (unsigned int)__dp4a((int)aS3, 0x01010101, 0);
    v[4] = (unsigned int)__dp4a((int)aN0, 0x01010101, 0);
    v[5] = (unsigned int)__dp4a((int)aN1, 0x01010101, 0);
    v[6] = (unsigned int)__dp4a((int)aN2, 0x01010101, 0);
    v[7] = (unsigned int)__dp4a((int)aN3, 0x01010101, 0);
    v[8] = (unsigned int)__dp4a((int)aZ,  0x01010101, 0);

    __shared__ unsigned int sh[9];
    __shared__ bool is_last;
    if (threadIdx.x < 9) sh[threadIdx.x] = 0u;
    __syncthreads();

#pragma unroll
    for (int k = 0; k < 9; k++) {
        unsigned int w = __reduce_add_sync(0xFFFFFFFFu, v[k]);
        if ((threadIdx.x & 31) == 0) atomicAdd(&sh[k], w);
    }
    __syncthreads();
    if (threadIdx.x < 9) atomicAdd(&g_hist[threadIdx.x], sh[threadIdx.x]);

    // Last-block-done: the final arriving block computes dice + resets state.
    if (threadIdx.x == 0) {
        __threadfence();
        unsigned int old = atomicAdd(&g_done, 1u);
        is_last = (old == (unsigned int)(gridDim.x - 1));
    }
    __syncthreads();

    if (is_last && threadIdx.x == 0) {
        unsigned int S[5], Nm[5];
        unsigned int ss = 0, sn = 0;
#pragma unroll
        for (int c = 0; c < 4; c++) {
            S[c]  = g_hist[c];       ss += S[c];
            Nm[c] = g_hist[4 + c];   sn += Nm[c];
        }
        unsigned int Z = g_hist[8];
        S[4]  = 2u * (unsigned int)n_total - ss;   // den1[4]+den2[4]
        Nm[4] = Z - sn;

        float acc = 0.0f;
#pragma unroll
        for (int c = 0; c < 5; c++) {
            acc += 2.0f * (((float)Nm[c] + DICE_EPS) / ((float)S[c] + DICE_EPS));
        }
        out[0] = acc * 0.2f;

        // reset state for the next (graph-replayed) launch
#pragma unroll
        for (int k = 0; k < 12; k++) g_hist[k] = 0u;
        __threadfence();
        g_done = 0u;
    }
}

extern "C" void kernel_launch(void* const* d_in, const int* in_sizes, int n_in,
                              void* d_out, int out_size) {
    const float* pred = (const float*)d_in[0];  // [128,1,512,512] f32, values 0..4
    const int*   mask = (const int*)d_in[1];    // [1,128,512,512] i32, values 0..4
    int n = in_sizes[0];                        // 33,554,432
    int nvec = n >> 2;                          // 8,388,608 16B groups

    dice_main_kernel<<<GRID_BLOCKS, 256>>>((const ulonglong2*)pred,
                                           (const int4*)mask,
                                           nvec, n, (float*)d_out);
}